// round 16
// baseline (speedup 1.0000x reference)
#include <cuda_runtime.h>
#include <cuda_fp16.h>
#include <cstdint>

#define B_ 2
#define T_ 2048
#define D_ 1024
#define H_ 16
#define DK_ 64
#define M_ (B_*T_)
#define DD_ (D_*D_)
#define SCALE_ 0.125f
#define QSCALE_ 0.1803368801111144f   // SCALE_ * log2(e)

// ---------------- scratch ----------------
__device__ float  g_Q[M_*D_];
__device__ float  g_K[M_*D_];
__device__ float  g_V[M_*D_];
__device__ __half g_Ah[3*M_*D_];   // input hi planes (q,k,v)
__device__ __half g_Al[3*M_*D_];   // input lo planes
__device__ __half g_Wh[4*DD_];     // fp16 weights (Wq,Wk,Wv,Wo)
__device__ __half g_Ch[M_*D_];     // CTX hi plane (written by attention)
__device__ __half g_Cl[M_*D_];     // CTX lo plane
__device__ float  g_bias[M_];
__device__ int    g_maskmode;

// ---------------- mask dtype detection ----------------
__global__ void detect_mask_kernel(const unsigned int* __restrict__ w) {
    __shared__ int s_badint, s_badfloat;
    if (threadIdx.x == 0) { s_badint = 0; s_badfloat = 0; }
    __syncthreads();
    int bi = 0, bf = 0;
    for (int i = threadIdx.x; i < 1024; i += blockDim.x) {
        unsigned v = w[i];
        if (v > 1u) bi = 1;
        if (v != 0u && v != 0x3F800000u) bf = 1;
    }
    if (bi) atomicOr(&s_badint, 1);
    if (bf) atomicOr(&s_badfloat, 1);
    __syncthreads();
    if (threadIdx.x == 0)
        g_maskmode = (!s_badint) ? 0 : ((!s_badfloat) ? 1 : 2);
}

__global__ void build_bias_kernel(const void* __restrict__ mask) {
    int i = blockIdx.x * blockDim.x + threadIdx.x;
    if (i >= M_) return;
    int mode = g_maskmode;
    bool keep;
    if (mode == 0)      keep = ((const int*)mask)[i] != 0;
    else if (mode == 1) keep = ((const float*)mask)[i] != 0.0f;
    else                keep = ((const unsigned char*)mask)[i] != 0;
    g_bias[i] = keep ? 0.0f : -1e30f;
}

// ---------------- helpers ----------------
__device__ __forceinline__ void mma_f16(float* d, const uint32_t* a, const uint32_t* b) {
    asm volatile(
        "mma.sync.aligned.m16n8k16.row.col.f32.f16.f16.f32 "
        "{%0,%1,%2,%3}, {%4,%5,%6,%7}, {%8,%9}, {%0,%1,%2,%3};"
        : "+f"(d[0]), "+f"(d[1]), "+f"(d[2]), "+f"(d[3])
        : "r"(a[0]), "r"(a[1]), "r"(a[2]), "r"(a[3]), "r"(b[0]), "r"(b[1]));
}

__device__ __forceinline__ void ldsm4(uint32_t& r0, uint32_t& r1, uint32_t& r2, uint32_t& r3,
                                      uint32_t saddr) {
    asm volatile("ldmatrix.sync.aligned.m8n8.x4.shared.b16 {%0,%1,%2,%3}, [%4];"
                 : "=r"(r0), "=r"(r1), "=r"(r2), "=r"(r3) : "r"(saddr));
}

__device__ __forceinline__ void split_h(float x, float& h, float& l) {
    h = __half2float(__float2half_rn(x));
    l = x - h;
}

__device__ __forceinline__ uint32_t packh(float a, float b) {
    __half2 t = __floats2half2_rn(a, b);   // low half = a
    return *reinterpret_cast<uint32_t*>(&t);
}

__device__ __forceinline__ uint32_t smem_u32(const void* p) {
    return (uint32_t)__cvta_generic_to_shared(p);
}

__device__ __forceinline__ void cp_async16(uint32_t dst, const void* src) {
    asm volatile("cp.async.cg.shared.global [%0], [%1], 16;" :: "r"(dst), "l"(src));
}

// ---------------- pre-conversion kernels ----------------
struct SplitBatch { const float* in[3]; __half* hi[3]; __half* lo[3]; };

__global__ void split_planes_kernel(SplitBatch sb) {
    const float* in = sb.in[blockIdx.z];
    __half* hi = sb.hi[blockIdx.z];
    __half* lo = sb.lo[blockIdx.z];
    int i = (blockIdx.x * 256 + threadIdx.x) * 4;
    float4 x = *(const float4*)(in + i);
    float h0,h1,h2,h3,l0,l1,l2,l3;
    split_h(x.x,h0,l0); split_h(x.y,h1,l1);
    split_h(x.z,h2,l2); split_h(x.w,h3,l3);
    *(uint2*)(hi + i) = make_uint2(packh(h0,h1), packh(h2,h3));
    *(uint2*)(lo + i) = make_uint2(packh(l0,l1), packh(l2,l3));
}

struct RoundBatch { const float* in[4]; };

__global__ void round_weights_kernel(RoundBatch rb, __half* out) {
    const float* in = rb.in[blockIdx.z];
    int i = (blockIdx.x * 256 + threadIdx.x) * 4;
    float4 x = *(const float4*)(in + i);
    *(uint2*)(out + (size_t)blockIdx.z * DD_ + i) =
        make_uint2(packh(x.x, x.y), packh(x.z, x.w));
}

// ================= fp16 x2 GEMM, pre-converted operands, cp.async fills =====
// C = (Ah+Al) @ Wh^T + b. 128x128 tile, 8 warps (2m x 4n), k-step 16.
#define GST 12

struct GemmBatchH {
    const __half* Ah[3]; const __half* Al[3]; const __half* Wh[3];
    const float* bias[3]; float* C[3];
};

__global__ __launch_bounds__(256, 2) void gemm_h_kernel(GemmBatchH gb)
{
    __shared__ __align__(16) uint32_t Ahs[2][128 * GST];
    __shared__ __align__(16) uint32_t Als[2][128 * GST];
    __shared__ __align__(16) uint32_t Bhs[2][128 * GST];

    const int bz = blockIdx.z;
    const __half* __restrict__ Ah = gb.Ah[bz];
    const __half* __restrict__ Al = gb.Al[bz];
    const __half* __restrict__ Wh = gb.Wh[bz];
    const float*  __restrict__ bvec = gb.bias[bz];
    float* __restrict__ C = gb.C[bz];

    const int tid  = threadIdx.x;
    const int lane = tid & 31, wid = tid >> 5;
    const int wm   = (wid >> 2) * 64;
    const int wn   = (wid & 3) * 32;
    const int gid  = lane >> 2, tig = lane & 3;
    const int m0 = blockIdx.y * 128;
    const int n0 = blockIdx.x * 128;

    float acc[4][4][4];
#pragma unroll
    for (int mt = 0; mt < 4; mt++)
#pragma unroll
        for (int nt = 0; nt < 4; nt++)
#pragma unroll
            for (int i = 0; i < 4; i++) acc[mt][nt][i] = 0.f;

    const int frow = tid >> 1;            // 0..127
    const int kh   = tid & 1;             // 8-half group within k16
    const __half* pAh = Ah + (size_t)(m0 + frow) * 1024 + kh * 8;
    const __half* pAl = Al + (size_t)(m0 + frow) * 1024 + kh * 8;
    const __half* pWh = Wh + (size_t)(n0 + frow) * 1024 + kh * 8;
    const uint32_t dOff = (uint32_t)((frow * GST + kh * 4) * 4);

    const uint32_t aOff = ((lane & 15) * GST + (lane >> 4) * 4) * 4;
    const uint32_t bOff = ((((lane >> 4) * 8) + (lane & 7)) * GST + ((lane >> 3) & 1) * 4) * 4;

    const uint32_t sAh = smem_u32(Ahs), sAl = smem_u32(Als);
    const uint32_t sBh = smem_u32(Bhs);
    const uint32_t PBUF = 128 * GST * 4;

#define GFILL(BUF, c)                                                         \
    do {                                                                      \
        cp_async16(sAh + (BUF) * PBUF + dOff, pAh + (size_t)(c) * 16);        \
        cp_async16(sAl + (BUF) * PBUF + dOff, pAl + (size_t)(c) * 16);        \
        cp_async16(sBh + (BUF) * PBUF + dOff, pWh + (size_t)(c) * 16);        \
        asm volatile("cp.async.commit_group;" ::: "memory");                  \
    } while (0)

#define GCOMP(BUF)                                                            \
    do {                                                                      \
        uint32_t a_h[4][4], a_l[4][4], b_h[4][2];                             \
        _Pragma("unroll")                                                     \
        for (int mt = 0; mt < 4; mt++) {                                      \
            uint32_t ro = (uint32_t)((wm + mt * 16) * GST * 4);               \
            ldsm4(a_h[mt][0], a_h[mt][1], a_h[mt][2], a_h[mt][3],             \
                  sAh + (BUF) * PBUF + ro + aOff);                            \
            ldsm4(a_l[mt][0], a_l[mt][1], a_l[mt][2], a_l[mt][3],             \
                  sAl + (BUF) * PBUF + ro + aOff);                            \
        }                                                                     \
        _Pragma("unroll")                                                     \
        for (int ntp = 0; ntp < 2; ntp++) {                                   \
            uint32_t ro = (uint32_t)((wn + ntp * 16) * GST * 4);              \
            ldsm4(b_h[2*ntp][0], b_h[2*ntp][1], b_h[2*ntp+1][0], b_h[2*ntp+1][1], \
                  sBh + (BUF) * PBUF + ro + bOff);                            \
        }                                                                     \
        _Pragma("unroll")                                                     \
        for (int mt = 0; mt < 4; mt++)                                        \
            _Pragma("unroll")                                                 \
            for (int nt = 0; nt < 4; nt++) {                                  \
                mma_f16(acc[mt][nt], a_h[mt], b_h[nt]);                       \
                mma_f16(acc[mt][nt], a_l[mt], b_h[nt]);                       \
            }                                                                 \
    } while (0)

    GFILL(0, 0);
    asm volatile("cp.async.wait_group 0;" ::: "memory");
    __syncthreads();

    int buf = 0;
    for (int c = 1; c < 64; c++) {
        GFILL(buf ^ 1, c);
        GCOMP(buf);
        asm volatile("cp.async.wait_group 0;" ::: "memory");
        __syncthreads();
        buf ^= 1;
    }
    GCOMP(buf);

#pragma unroll
    for (int mt = 0; mt < 4; mt++) {
#pragma unroll
        for (int nt = 0; nt < 4; nt++) {
            int gm = m0 + wm + mt * 16 + gid;
            int gn = n0 + wn + nt * 8 + tig * 2;
            float b0 = __ldg(bvec + gn);
            float b1 = __ldg(bvec + gn + 1);
            *(float2*)&C[(size_t)gm * 1024 + gn] =
                make_float2(acc[mt][nt][0] + b0, acc[mt][nt][1] + b1);
            *(float2*)&C[(size_t)(gm + 8) * 1024 + gn] =
                make_float2(acc[mt][nt][2] + b0, acc[mt][nt][3] + b1);
        }
    }
}

// ================= tensor-core flash attention (R15 validated) ==============
// QK^T: fp16 x1, SCALE*log2e folded into Q; exp2 softmax.
// P*V: fp16 x1, P from S C-frags in registers. Epilogue writes CTX hi/lo planes.
#define KSTR 40
#define AVSTR 72

__global__ __launch_bounds__(256) void attn_mma_kernel(
    const float* __restrict__ Qg, const float* __restrict__ Kg,
    const float* __restrict__ Vg, __half* __restrict__ Ch,
    __half* __restrict__ Cl)
{
    __shared__ __align__(16) uint32_t Kw[32 * KSTR];
    __shared__ uint32_t Vh[16 * AVSTR];
    __shared__ float    Bs[32];

    const int tid  = threadIdx.x;
    const int lane = tid & 31, wid = tid >> 5;
    const int gid  = lane >> 2, tig = lane & 3;
    const int b = blockIdx.z, h = blockIdx.y;
    const int t0 = blockIdx.x * 128;

    const size_t kvBase = ((size_t)b * T_) * D_ + h * DK_;

    uint32_t Qr[4][4];
    {
        const int r0 = t0 + wid * 16 + gid;
        const float* q0 = Qg + ((size_t)(b * T_) + r0) * D_ + h * DK_;
        const float* q1 = q0 + 8 * D_;
#pragma unroll
        for (int ks = 0; ks < 4; ks++) {
            int c = ks * 16 + 2 * tig;
            Qr[ks][0] = packh(q0[c] * QSCALE_,     q0[c + 1] * QSCALE_);
            Qr[ks][1] = packh(q1[c] * QSCALE_,     q1[c + 1] * QSCALE_);
            Qr[ks][2] = packh(q0[c + 8] * QSCALE_, q0[c + 9] * QSCALE_);
            Qr[ks][3] = packh(q1[c + 8] * QSCALE_, q1[c + 9] * QSCALE_);
        }
    }

    float oacc[8][4];
#pragma unroll
    for (int nt = 0; nt < 8; nt++)
#pragma unroll
        for (int i = 0; i < 4; i++) oacc[nt][i] = 0.f;
    float m0 = -1e30f, m1 = -1e30f, l0 = 0.f, l1 = 0.f;

    const int frow = tid >> 4;
    const int fc4  = (tid & 15) * 4;
    const float* kRow = Kg + kvBase + (size_t)frow * D_ + fc4;

    const int vp  = tid >> 4;
    const int vcg = (tid & 15) * 4;
    const float* vRow0 = Vg + kvBase + (size_t)(2 * vp) * D_ + vcg;
    const float* vRow1 = vRow0 + D_;

    const int jw = fc4 >> 1;
    const int w0 = jw & 7, w1 = (jw + 1) & 7;
    const int kp0 = (jw & ~7) + ((w0 < 4) ? 2 * w0 : 2 * w0 - 7);
    const int kp1 = (jw & ~7) + ((w1 < 4) ? 2 * w1 : 2 * w1 - 7);

    float4 ka  = *(const float4*)(kRow);
    float4 kb4 = *(const float4*)(kRow + 16 * D_);
    float4 va0 = *(const float4*)(vRow0);
    float4 va1 = *(const float4*)(vRow1);

    for (int s0 = 0; s0 < T_; s0 += 32) {
        __syncthreads();
        {
            uint32_t* kr0 = &Kw[frow * KSTR];
            kr0[kp0] = packh(ka.x, ka.y);
            kr0[kp1] = packh(ka.z, ka.w);
            uint32_t* kr1 = &Kw[(frow + 16) * KSTR];
            kr1[kp0] = packh(kb4.x, kb4.y);
            kr1[kp1] = packh(kb4.z, kb4.w);

            uint32_t* vhp = &Vh[vp * AVSTR + vcg];
            vhp[0] = packh(va0.x, va1.x);
            vhp[1] = packh(va0.y, va1.y);
            vhp[2] = packh(va0.z, va1.z);
            vhp[3] = packh(va0.w, va1.w);

            if (tid < 32) Bs[tid] = g_bias[b * T_ + s0 + tid];
        }
        __syncthreads();

        if (s0 + 32 < T_) {
            ka  = *(const float4*)(kRow + (size_t)(s0 + 32) * D_);
            kb4 = *(const float4*)(kRow + (size_t)(s0 + 48) * D_);
            va0 = *(const float4*)(vRow0 + (size_t)(s0 + 32) * D_);
            va1 = *(const float4*)(vRow1 + (size_t)(s0 + 32) * D_);
        }

        float sv[4][4];
#pragma unroll
        for (int nt = 0; nt < 4; nt++)
#pragma unroll
            for (int i = 0; i < 4; i++) sv[nt][i] = 0.f;
#pragma unroll
        for (int ks = 0; ks < 4; ks++) {
#pragma unroll
            for (int nt = 0; nt < 4; nt++) {
                uint2 bb = *(const uint2*)&Kw[(nt * 8 + gid) * KSTR + ks * 8 + 2 * tig];
                uint32_t bh[2] = { bb.x, bb.y };
                mma_f16(sv[nt], Qr[ks], bh);
            }
        }

#pragma unroll
        for (int nt = 0; nt < 4; nt++) {
            int c0 = nt * 8 + 2 * tig;
            float bb0 = Bs[c0], bb1 = Bs[c0 + 1];
            sv[nt][0] += bb0;
            sv[nt][1] += bb1;
            sv[nt][2] += bb0;
            sv[nt][3] += bb1;
        }
        float mx0 = fmaxf(fmaxf(sv[0][0], sv[0][1]), fmaxf(sv[1][0], sv[1][1]));
        mx0 = fmaxf(mx0, fmaxf(fmaxf(sv[2][0], sv[2][1]), fmaxf(sv[3][0], sv[3][1])));
        float mx1 = fmaxf(fmaxf(sv[0][2], sv[0][3]), fmaxf(sv[1][2], sv[1][3]));
        mx1 = fmaxf(mx1, fmaxf(fmaxf(sv[2][2], sv[2][3]), fmaxf(sv[3][2], sv[3][3])));
        mx0 = fmaxf(mx0, __shfl_xor_sync(0xffffffffu, mx0, 1));
        mx0 = fmaxf(mx0, __shfl_xor_sync(0xffffffffu, mx0, 2));
        mx1 = fmaxf(mx1, __shfl_xor_sync(0xffffffffu, mx1, 1));
        mx1 = fmaxf(mx1, __shfl_xor_sync(0xffffffffu, mx1, 2));

        float m0n = fmaxf(m0, mx0), m1n = fmaxf(m1, mx1);
        float c0f = exp2f(m0 - m0n), c1f = exp2f(m1 - m1n);
        m0 = m0n; m1 = m1n;

        float rs0 = 0.f, rs1 = 0.f;
#pragma unroll
        for (int nt = 0; nt < 4; nt++) {
            float p0 = exp2f(sv[nt][0] - m0n);
            float p1 = exp2f(sv[nt][1] - m0n);
            float p2 = exp2f(sv[nt][2] - m1n);
            float p3 = exp2f(sv[nt][3] - m1n);
            rs0 += p0 + p1; rs1 += p2 + p3;
            sv[nt][0] = p0; sv[nt][1] = p1;
            sv[nt][2] = p2; sv[nt][3] = p3;
        }
        rs0 += __shfl_xor_sync(0xffffffffu, rs0, 1);
        rs0 += __shfl_xor_sync(0xffffffffu, rs0, 2);
        rs1 += __shfl_xor_sync(0xffffffffu, rs1, 1);
        rs1 += __shfl_xor_sync(0xffffffffu, rs1, 2);
        l0 = l0 * c0f + rs0;
        l1 = l1 * c1f + rs1;
#pragma unroll
        for (int nt = 0; nt < 8; nt++) {
            oacc[nt][0] *= c0f; oacc[nt][1] *= c0f;
            oacc[nt][2] *= c1f; oacc[nt][3] *= c1f;
        }

#pragma unroll
        for (int kk = 0; kk < 2; kk++) {
            uint32_t ah[4];
            ah[0] = packh(sv[2 * kk][0],     sv[2 * kk][1]);
            ah[1] = packh(sv[2 * kk][2],     sv[2 * kk][3]);
            ah[2] = packh(sv[2 * kk + 1][0], sv[2 * kk + 1][1]);
            ah[3] = packh(sv[2 * kk + 1][2], sv[2 * kk + 1][3]);
#pragma unroll
            for (int nt = 0; nt < 8; nt++) {
                uint32_t bh[2];
                bh[0] = Vh[(kk * 8 + tig) * AVSTR + nt * 8 + gid];
                bh[1] = Vh[(kk * 8 + tig + 4) * AVSTR + nt * 8 + gid];
                mma_f16(oacc[nt], ah, bh);
            }
        }
    }

    // epilogue: write CTX as hi/lo fp16 planes (split moved here from O-proj fill)
    float inv0 = 1.f / l0, inv1 = 1.f / l1;
    const int gr0 = t0 + wid * 16 + gid;
    const size_t o0 = ((size_t)(b * T_) + gr0) * D_ + h * DK_;
    const size_t o1 = o0 + 8 * D_;
#pragma unroll
    for (int nt = 0; nt < 8; nt++) {
        int c = nt * 8 + 2 * tig;
        float h0, lo0, h1, lo1;
        split_h(oacc[nt][0] * inv0, h0, lo0);
        split_h(oacc[nt][1] * inv0, h1, lo1);
        *(uint32_t*)(Ch + o0 + c) = packh(h0, h1);
        *(uint32_t*)(Cl + o0 + c) = packh(lo0, lo1);
        split_h(oacc[nt][2] * inv1, h0, lo0);
        split_h(oacc[nt][3] * inv1, h1, lo1);
        *(uint32_t*)(Ch + o1 + c) = packh(h0, h1);
        *(uint32_t*)(Cl + o1 + c) = packh(lo0, lo1);
    }
}

// ---------------- launch ----------------
extern "C" void kernel_launch(void* const* d_in, const int* in_sizes, int n_in,
                              void* d_out, int out_size)
{
    const float* query = (const float*)d_in[0];
    const float* key   = (const float*)d_in[1];
    const float* value = (const float*)d_in[2];
    const void*  mask  = d_in[3];
    const float* Wq = (const float*)d_in[4];  const float* bq = (const float*)d_in[5];
    const float* Wk = (const float*)d_in[6];  const float* bk = (const float*)d_in[7];
    const float* Wv = (const float*)d_in[8];  const float* bv = (const float*)d_in[9];
    const float* Wo = (const float*)d_in[10]; const float* bo = (const float*)d_in[11];

    float *Qb, *Kb, *Vb;
    __half *Ahb, *Alb, *Whb, *Chb, *Clb;
    cudaGetSymbolAddress((void**)&Qb, g_Q);
    cudaGetSymbolAddress((void**)&Kb, g_K);
    cudaGetSymbolAddress((void**)&Vb, g_V);
    cudaGetSymbolAddress((void**)&Ahb, g_Ah);
    cudaGetSymbolAddress((void**)&Alb, g_Al);
    cudaGetSymbolAddress((void**)&Whb, g_Wh);
    cudaGetSymbolAddress((void**)&Chb, g_Ch);
    cudaGetSymbolAddress((void**)&Clb, g_Cl);

    detect_mask_kernel<<<1, 256>>>((const unsigned int*)mask);
    build_bias_kernel<<<(M_ + 255) / 256, 256>>>(mask);

    // pre-convert inputs (hi/lo planes) and weights (fp16)
    SplitBatch sb;
    sb.in[0] = query; sb.in[1] = key; sb.in[2] = value;
    sb.hi[0] = Ahb;            sb.lo[0] = Alb;
    sb.hi[1] = Ahb + M_*D_;    sb.lo[1] = Alb + M_*D_;
    sb.hi[2] = Ahb + 2*M_*D_;  sb.lo[2] = Alb + 2*M_*D_;
    split_planes_kernel<<<dim3(M_*D_/1024, 1, 3), 256>>>(sb);

    RoundBatch rbw;
    rbw.in[0] = Wq; rbw.in[1] = Wk; rbw.in[2] = Wv; rbw.in[3] = Wo;
    round_weights_kernel<<<dim3(DD_/1024, 1, 4), 256>>>(rbw, Whb);

    // QKV projections (batched)
    GemmBatchH gqkv;
    gqkv.Ah[0] = Ahb;           gqkv.Al[0] = Alb;
    gqkv.Ah[1] = Ahb + M_*D_;   gqkv.Al[1] = Alb + M_*D_;
    gqkv.Ah[2] = Ahb + 2*M_*D_; gqkv.Al[2] = Alb + 2*M_*D_;
    gqkv.Wh[0] = Whb;           gqkv.Wh[1] = Whb + DD_; gqkv.Wh[2] = Whb + 2*DD_;
    gqkv.bias[0] = bq; gqkv.bias[1] = bk; gqkv.bias[2] = bv;
    gqkv.C[0] = Qb; gqkv.C[1] = Kb; gqkv.C[2] = Vb;
    gemm_h_kernel<<<dim3(D_/128, M_/128, 3), 256>>>(gqkv);

    attn_mma_kernel<<<dim3(T_/128, H_, B_), 256>>>(Qb, Kb, Vb, Chb, Clb);

    // O projection
    GemmBatchH go;
    go.Ah[0] = Chb; go.Al[0] = Clb; go.Wh[0] = Whb + 3*DD_;
    go.bias[0] = bo; go.C[0] = (float*)d_out;
    go.Ah[1] = Chb; go.Al[1] = Clb; go.Wh[1] = Whb + 3*DD_;
    go.bias[1] = bo; go.C[1] = (float*)d_out;
    go.Ah[2] = Chb; go.Al[2] = Clb; go.Wh[2] = Whb + 3*DD_;
    go.bias[2] = bo; go.C[2] = (float*)d_out;
    gemm_h_kernel<<<dim3(D_/128, M_/128, 1), 256>>>(go);
}

// round 17
// speedup vs baseline: 1.5000x; 1.5000x over previous
#include <cuda_runtime.h>
#include <cuda_fp16.h>
#include <cstdint>

#define B_ 2
#define T_ 2048
#define D_ 1024
#define H_ 16
#define DK_ 64
#define M_ (B_*T_)
#define DD_ (D_*D_)
#define SCALE_ 0.125f
#define QSCALE_ 0.1803368801111144f   // SCALE_ * log2(e)

// ---------------- scratch ----------------
__device__ float  g_Q[M_*D_];
__device__ float  g_K[M_*D_];
__device__ float  g_V[M_*D_];
__device__ __half g_Wh[4*DD_];     // fp16 weights (Wq,Wk,Wv,Wo)
__device__ __half g_Ch[M_*D_];     // CTX hi plane (from attention)
__device__ __half g_Cl[M_*D_];     // CTX lo plane
__device__ float  g_bias[M_];
__device__ int    g_maskmode;

// ---------------- mask dtype detection ----------------
__global__ void detect_mask_kernel(const unsigned int* __restrict__ w) {
    __shared__ int s_badint, s_badfloat;
    if (threadIdx.x == 0) { s_badint = 0; s_badfloat = 0; }
    __syncthreads();
    int bi = 0, bf = 0;
    for (int i = threadIdx.x; i < 1024; i += blockDim.x) {
        unsigned v = w[i];
        if (v > 1u) bi = 1;
        if (v != 0u && v != 0x3F800000u) bf = 1;
    }
    if (bi) atomicOr(&s_badint, 1);
    if (bf) atomicOr(&s_badfloat, 1);
    __syncthreads();
    if (threadIdx.x == 0)
        g_maskmode = (!s_badint) ? 0 : ((!s_badfloat) ? 1 : 2);
}

__global__ void build_bias_kernel(const void* __restrict__ mask) {
    int i = blockIdx.x * blockDim.x + threadIdx.x;
    if (i >= M_) return;
    int mode = g_maskmode;
    bool keep;
    if (mode == 0)      keep = ((const int*)mask)[i] != 0;
    else if (mode == 1) keep = ((const float*)mask)[i] != 0.0f;
    else                keep = ((const unsigned char*)mask)[i] != 0;
    g_bias[i] = keep ? 0.0f : -1e30f;
}

// ---------------- helpers ----------------
__device__ __forceinline__ void mma_f16(float* d, const uint32_t* a, const uint32_t* b) {
    asm volatile(
        "mma.sync.aligned.m16n8k16.row.col.f32.f16.f16.f32 "
        "{%0,%1,%2,%3}, {%4,%5,%6,%7}, {%8,%9}, {%0,%1,%2,%3};"
        : "+f"(d[0]), "+f"(d[1]), "+f"(d[2]), "+f"(d[3])
        : "r"(a[0]), "r"(a[1]), "r"(a[2]), "r"(a[3]), "r"(b[0]), "r"(b[1]));
}

__device__ __forceinline__ void ldsm4(uint32_t& r0, uint32_t& r1, uint32_t& r2, uint32_t& r3,
                                      uint32_t saddr) {
    asm volatile("ldmatrix.sync.aligned.m8n8.x4.shared.b16 {%0,%1,%2,%3}, [%4];"
                 : "=r"(r0), "=r"(r1), "=r"(r2), "=r"(r3) : "r"(saddr));
}

__device__ __forceinline__ void split_h(float x, float& h, float& l) {
    h = __half2float(__float2half_rn(x));
    l = x - h;
}

__device__ __forceinline__ uint32_t packh(float a, float b) {
    __half2 t = __floats2half2_rn(a, b);   // low half = a
    return *reinterpret_cast<uint32_t*>(&t);
}

__device__ __forceinline__ uint32_t smem_u32(const void* p) {
    return (uint32_t)__cvta_generic_to_shared(p);
}

// ---------------- weight pre-round (once; ~17us) ----------------
struct RoundBatch { const float* in[4]; };

__global__ void round_weights_kernel(RoundBatch rb, __half* out) {
    const float* in = rb.in[blockIdx.z];
    int i = (blockIdx.x * 256 + threadIdx.x) * 4;
    float4 x = *(const float4*)(in + i);
    *(uint2*)(out + (size_t)blockIdx.z * DD_ + i) =
        make_uint2(packh(x.x, x.y), packh(x.z, x.w));
}

// ================= fp16 x2 GEMM, 128x128 tile, ldmatrix frags ==================
// C = (Ah+Al) @ Wh^T + b. 8 warps (2m x 4n), k-step 16. W is pre-rounded fp16.
// AHALF=0: A fp32, split in fill. AHALF=1: A pre-split hi/lo half planes.
#define GST 12

struct GemmBatch {
    const void* A[3];     // fp32 A (AHALF=0) or hi plane (AHALF=1)
    const void* Al[3];    // lo plane (AHALF=1 only)
    const __half* Wh[3];
    const float* bias[3];
    float* C[3];
};

template<int AHALF>
__global__ __launch_bounds__(256, 2) void gemm_f16x2_kernel(GemmBatch gb)
{
    __shared__ __align__(16) uint32_t Ahs[2][128 * GST];
    __shared__ __align__(16) uint32_t Als[2][128 * GST];
    __shared__ __align__(16) uint32_t Bhs[2][128 * GST];

    const int bz = blockIdx.z;
    const float*  __restrict__ Af  = (const float*)gb.A[bz];
    const __half* __restrict__ Ahp = (const __half*)gb.A[bz];
    const __half* __restrict__ Alp = (const __half*)gb.Al[bz];
    const __half* __restrict__ Wh  = gb.Wh[bz];
    const float*  __restrict__ bvec = gb.bias[bz];
    float* __restrict__ C = gb.C[bz];

    const int tid  = threadIdx.x;
    const int lane = tid & 31, wid = tid >> 5;
    const int wm   = (wid >> 2) * 64;
    const int wn   = (wid & 3) * 32;
    const int gid  = lane >> 2, tig = lane & 3;
    const int m0 = blockIdx.y * 128;
    const int n0 = blockIdx.x * 128;

    float acc[4][4][4];
#pragma unroll
    for (int mt = 0; mt < 4; mt++)
#pragma unroll
        for (int nt = 0; nt < 4; nt++)
#pragma unroll
            for (int i = 0; i < 4; i++) acc[mt][nt][i] = 0.f;

    const int frow = tid >> 1;
    const int kh   = tid & 1;
    const float*  Agf = Af  + (size_t)(m0 + frow) * 1024 + kh * 8;
    const __half* Agh = Ahp + (size_t)(m0 + frow) * 1024 + kh * 8;
    const __half* Agl = Alp + (size_t)(m0 + frow) * 1024 + kh * 8;
    const __half* Wg  = Wh  + (size_t)(n0 + frow) * 1024 + kh * 8;

    const uint32_t aOff = ((lane & 15) * GST + (lane >> 4) * 4) * 4;
    const uint32_t bOff = ((((lane >> 4) * 8) + (lane & 7)) * GST + ((lane >> 3) & 1) * 4) * 4;

    const uint32_t sAh = smem_u32(Ahs), sAl = smem_u32(Als);
    const uint32_t sBh = smem_u32(Bhs);
    const uint32_t PBUF = 128 * GST * 4;

    // prefetch registers
    float4 pa0, pa1;
    uint4  pah, pal, pw;
    if (AHALF) {
        pah = *(const uint4*)(Agh);
        pal = *(const uint4*)(Agl);
    } else {
        pa0 = *(const float4*)(Agf);
        pa1 = *(const float4*)(Agf + 4);
    }
    pw = *(const uint4*)(Wg);

#define GSTORE(BUF)                                                            \
    do {                                                                       \
        if (AHALF) {                                                           \
            *(uint4*)&Ahs[BUF][frow*GST + kh*4] = pah;                         \
            *(uint4*)&Als[BUF][frow*GST + kh*4] = pal;                         \
        } else {                                                               \
            float h0,h1,h2,h3,h4,h5,h6,h7,l0,l1,l2,l3,l4,l5,l6,l7;             \
            split_h(pa0.x,h0,l0); split_h(pa0.y,h1,l1);                        \
            split_h(pa0.z,h2,l2); split_h(pa0.w,h3,l3);                        \
            split_h(pa1.x,h4,l4); split_h(pa1.y,h5,l5);                        \
            split_h(pa1.z,h6,l6); split_h(pa1.w,h7,l7);                        \
            *(uint4*)&Ahs[BUF][frow*GST + kh*4] =                              \
                make_uint4(packh(h0,h1),packh(h2,h3),packh(h4,h5),packh(h6,h7)); \
            *(uint4*)&Als[BUF][frow*GST + kh*4] =                              \
                make_uint4(packh(l0,l1),packh(l2,l3),packh(l4,l5),packh(l6,l7)); \
        }                                                                      \
        *(uint4*)&Bhs[BUF][frow*GST + kh*4] = pw;                              \
    } while (0)

#define GCOMP(BUF)                                                            \
    do {                                                                      \
        uint32_t a_h[4][4], a_l[4][4], b_h[4][2];                             \
        _Pragma("unroll")                                                     \
        for (int mt = 0; mt < 4; mt++) {                                      \
            uint32_t ro = (uint32_t)((wm + mt * 16) * GST * 4);               \
            ldsm4(a_h[mt][0], a_h[mt][1], a_h[mt][2], a_h[mt][3],             \
                  sAh + (BUF) * PBUF + ro + aOff);                            \
            ldsm4(a_l[mt][0], a_l[mt][1], a_l[mt][2], a_l[mt][3],             \
                  sAl + (BUF) * PBUF + ro + aOff);                            \
        }                                                                     \
        _Pragma("unroll")                                                     \
        for (int ntp = 0; ntp < 2; ntp++) {                                   \
            uint32_t ro = (uint32_t)((wn + ntp * 16) * GST * 4);              \
            ldsm4(b_h[2*ntp][0], b_h[2*ntp][1], b_h[2*ntp+1][0], b_h[2*ntp+1][1], \
                  sBh + (BUF) * PBUF + ro + bOff);                            \
        }                                                                     \
        _Pragma("unroll")                                                     \
        for (int mt = 0; mt < 4; mt++)                                        \
            _Pragma("unroll")                                                 \
            for (int nt = 0; nt < 4; nt++) {                                  \
                mma_f16(acc[mt][nt], a_h[mt], b_h[nt]);                       \
                mma_f16(acc[mt][nt], a_l[mt], b_h[nt]);                       \
            }                                                                 \
    } while (0)

    GSTORE(0);
    __syncthreads();

    int buf = 0;
    for (int k0 = 16; k0 < 1024; k0 += 16) {
        if (AHALF) {
            pah = *(const uint4*)(Agh + k0);
            pal = *(const uint4*)(Agl + k0);
        } else {
            pa0 = *(const float4*)(Agf + k0);
            pa1 = *(const float4*)(Agf + k0 + 4);
        }
        pw = *(const uint4*)(Wg + k0);
        if (buf == 0) GCOMP(0); else GCOMP(1);
        __syncthreads();
        if (buf == 0) GSTORE(1); else GSTORE(0);
        __syncthreads();
        buf ^= 1;
    }
    if (buf == 0) GCOMP(0); else GCOMP(1);

#pragma unroll
    for (int mt = 0; mt < 4; mt++) {
#pragma unroll
        for (int nt = 0; nt < 4; nt++) {
            int gm = m0 + wm + mt * 16 + gid;
            int gn = n0 + wn + nt * 8 + tig * 2;
            float b0 = __ldg(bvec + gn);
            float b1 = __ldg(bvec + gn + 1);
            *(float2*)&C[(size_t)gm * 1024 + gn] =
                make_float2(acc[mt][nt][0] + b0, acc[mt][nt][1] + b1);
            *(float2*)&C[(size_t)(gm + 8) * 1024 + gn] =
                make_float2(acc[mt][nt][2] + b0, acc[mt][nt][3] + b1);
        }
    }
}

// ================= tensor-core flash attention (R15 validated) ==============
// QK^T: fp16 x1 (k16), SCALE*log2e folded into Q; exp2 softmax.
// P*V: fp16 x1, P from S C-frags in registers. Epilogue -> CTX hi/lo planes.
#define KSTR 40
#define AVSTR 72

__global__ __launch_bounds__(256) void attn_mma_kernel(
    const float* __restrict__ Qg, const float* __restrict__ Kg,
    const float* __restrict__ Vg, __half* __restrict__ Ch,
    __half* __restrict__ Cl)
{
    __shared__ __align__(16) uint32_t Kw[32 * KSTR];
    __shared__ uint32_t Vh[16 * AVSTR];
    __shared__ float    Bs[32];

    const int tid  = threadIdx.x;
    const int lane = tid & 31, wid = tid >> 5;
    const int gid  = lane >> 2, tig = lane & 3;
    const int b = blockIdx.z, h = blockIdx.y;
    const int t0 = blockIdx.x * 128;

    const size_t kvBase = ((size_t)b * T_) * D_ + h * DK_;

    uint32_t Qr[4][4];
    {
        const int r0 = t0 + wid * 16 + gid;
        const float* q0 = Qg + ((size_t)(b * T_) + r0) * D_ + h * DK_;
        const float* q1 = q0 + 8 * D_;
#pragma unroll
        for (int ks = 0; ks < 4; ks++) {
            int c = ks * 16 + 2 * tig;
            Qr[ks][0] = packh(q0[c] * QSCALE_,     q0[c + 1] * QSCALE_);
            Qr[ks][1] = packh(q1[c] * QSCALE_,     q1[c + 1] * QSCALE_);
            Qr[ks][2] = packh(q0[c + 8] * QSCALE_, q0[c + 9] * QSCALE_);
            Qr[ks][3] = packh(q1[c + 8] * QSCALE_, q1[c + 9] * QSCALE_);
        }
    }

    float oacc[8][4];
#pragma unroll
    for (int nt = 0; nt < 8; nt++)
#pragma unroll
        for (int i = 0; i < 4; i++) oacc[nt][i] = 0.f;
    float m0 = -1e30f, m1 = -1e30f, l0 = 0.f, l1 = 0.f;

    const int frow = tid >> 4;
    const int fc4  = (tid & 15) * 4;
    const float* kRow = Kg + kvBase + (size_t)frow * D_ + fc4;

    const int vp  = tid >> 4;
    const int vcg = (tid & 15) * 4;
    const float* vRow0 = Vg + kvBase + (size_t)(2 * vp) * D_ + vcg;
    const float* vRow1 = vRow0 + D_;

    const int jw = fc4 >> 1;
    const int w0 = jw & 7, w1 = (jw + 1) & 7;
    const int kp0 = (jw & ~7) + ((w0 < 4) ? 2 * w0 : 2 * w0 - 7);
    const int kp1 = (jw & ~7) + ((w1 < 4) ? 2 * w1 : 2 * w1 - 7);

    float4 ka  = *(const float4*)(kRow);
    float4 kb4 = *(const float4*)(kRow + 16 * D_);
    float4 va0 = *(const float4*)(vRow0);
    float4 va1 = *(const float4*)(vRow1);

    for (int s0 = 0; s0 < T_; s0 += 32) {
        __syncthreads();
        {
            uint32_t* kr0 = &Kw[frow * KSTR];
            kr0[kp0] = packh(ka.x, ka.y);
            kr0[kp1] = packh(ka.z, ka.w);
            uint32_t* kr1 = &Kw[(frow + 16) * KSTR];
            kr1[kp0] = packh(kb4.x, kb4.y);
            kr1[kp1] = packh(kb4.z, kb4.w);

            uint32_t* vhp = &Vh[vp * AVSTR + vcg];
            vhp[0] = packh(va0.x, va1.x);
            vhp[1] = packh(va0.y, va1.y);
            vhp[2] = packh(va0.z, va1.z);
            vhp[3] = packh(va0.w, va1.w);

            if (tid < 32) Bs[tid] = g_bias[b * T_ + s0 + tid];
        }
        __syncthreads();

        if (s0 + 32 < T_) {
            ka  = *(const float4*)(kRow + (size_t)(s0 + 32) * D_);
            kb4 = *(const float4*)(kRow + (size_t)(s0 + 48) * D_);
            va0 = *(const float4*)(vRow0 + (size_t)(s0 + 32) * D_);
            va1 = *(const float4*)(vRow1 + (size_t)(s0 + 32) * D_);
        }

        float sv[4][4];
#pragma unroll
        for (int nt = 0; nt < 4; nt++)
#pragma unroll
            for (int i = 0; i < 4; i++) sv[nt][i] = 0.f;
#pragma unroll
        for (int ks = 0; ks < 4; ks++) {
#pragma unroll
            for (int nt = 0; nt < 4; nt++) {
                uint2 bb = *(const uint2*)&Kw[(nt * 8 + gid) * KSTR + ks * 8 + 2 * tig];
                uint32_t bh[2] = { bb.x, bb.y };
                mma_f16(sv[nt], Qr[ks], bh);
            }
        }

#pragma unroll
        for (int nt = 0; nt < 4; nt++) {
            int c0 = nt * 8 + 2 * tig;
            float bb0 = Bs[c0], bb1 = Bs[c0 + 1];
            sv[nt][0] += bb0;
            sv[nt][1] += bb1;
            sv[nt][2] += bb0;
            sv[nt][3] += bb1;
        }
        float mx0 = fmaxf(fmaxf(sv[0][0], sv[0][1]), fmaxf(sv[1][0], sv[1][1]));
        mx0 = fmaxf(mx0, fmaxf(fmaxf(sv[2][0], sv[2][1]), fmaxf(sv[3][0], sv[3][1])));
        float mx1 = fmaxf(fmaxf(sv[0][2], sv[0][3]), fmaxf(sv[1][2], sv[1][3]));
        mx1 = fmaxf(mx1, fmaxf(fmaxf(sv[2][2], sv[2][3]), fmaxf(sv[3][2], sv[3][3])));
        mx0 = fmaxf(mx0, __shfl_xor_sync(0xffffffffu, mx0, 1));
        mx0 = fmaxf(mx0, __shfl_xor_sync(0xffffffffu, mx0, 2));
        mx1 = fmaxf(mx1, __shfl_xor_sync(0xffffffffu, mx1, 1));
        mx1 = fmaxf(mx1, __shfl_xor_sync(0xffffffffu, mx1, 2));

        float m0n = fmaxf(m0, mx0), m1n = fmaxf(m1, mx1);
        float c0f = exp2f(m0 - m0n), c1f = exp2f(m1 - m1n);
        m0 = m0n; m1 = m1n;

        float rs0 = 0.f, rs1 = 0.f;
#pragma unroll
        for (int nt = 0; nt < 4; nt++) {
            float p0 = exp2f(sv[nt][0] - m0n);
            float p1 = exp2f(sv[nt][1] - m0n);
            float p2 = exp2f(sv[nt][2] - m1n);
            float p3 = exp2f(sv[nt][3] - m1n);
            rs0 += p0 + p1; rs1 += p2 + p3;
            sv[nt][0] = p0; sv[nt][1] = p1;
            sv[nt][2] = p2; sv[nt][3] = p3;
        }
        rs0 += __shfl_xor_sync(0xffffffffu, rs0, 1);
        rs0 += __shfl_xor_sync(0xffffffffu, rs0, 2);
        rs1 += __shfl_xor_sync(0xffffffffu, rs1, 1);
        rs1 += __shfl_xor_sync(0xffffffffu, rs1, 2);
        l0 = l0 * c0f + rs0;
        l1 = l1 * c1f + rs1;
#pragma unroll
        for (int nt = 0; nt < 8; nt++) {
            oacc[nt][0] *= c0f; oacc[nt][1] *= c0f;
            oacc[nt][2] *= c1f; oacc[nt][3] *= c1f;
        }

#pragma unroll
        for (int kk = 0; kk < 2; kk++) {
            uint32_t ah[4];
            ah[0] = packh(sv[2 * kk][0],     sv[2 * kk][1]);
            ah[1] = packh(sv[2 * kk][2],     sv[2 * kk][3]);
            ah[2] = packh(sv[2 * kk + 1][0], sv[2 * kk + 1][1]);
            ah[3] = packh(sv[2 * kk + 1][2], sv[2 * kk + 1][3]);
#pragma unroll
            for (int nt = 0; nt < 8; nt++) {
                uint32_t bh[2];
                bh[0] = Vh[(kk * 8 + tig) * AVSTR + nt * 8 + gid];
                bh[1] = Vh[(kk * 8 + tig + 4) * AVSTR + nt * 8 + gid];
                mma_f16(oacc[nt], ah, bh);
            }
        }
    }

    // epilogue: CTX as hi/lo fp16 planes (split hoisted from O-proj fill)
    float inv0 = 1.f / l0, inv1 = 1.f / l1;
    const int gr0 = t0 + wid * 16 + gid;
    const size_t o0 = ((size_t)(b * T_) + gr0) * D_ + h * DK_;
    const size_t o1 = o0 + 8 * D_;
#pragma unroll
    for (int nt = 0; nt < 8; nt++) {
        int c = nt * 8 + 2 * tig;
        float h0, lo0, h1, lo1;
        split_h(oacc[nt][0] * inv0, h0, lo0);
        split_h(oacc[nt][1] * inv0, h1, lo1);
        *(uint32_t*)(Ch + o0 + c) = packh(h0, h1);
        *(uint32_t*)(Cl + o0 + c) = packh(lo0, lo1);
        split_h(oacc[nt][2] * inv1, h0, lo0);
        split_h(oacc[nt][3] * inv1, h1, lo1);
        *(uint32_t*)(Ch + o1 + c) = packh(h0, h1);
        *(uint32_t*)(Cl + o1 + c) = packh(lo0, lo1);
    }
}

// ---------------- launch ----------------
extern "C" void kernel_launch(void* const* d_in, const int* in_sizes, int n_in,
                              void* d_out, int out_size)
{
    const float* query = (const float*)d_in[0];
    const float* key   = (const float*)d_in[1];
    const float* value = (const float*)d_in[2];
    const void*  mask  = d_in[3];
    const float* Wq = (const float*)d_in[4];  const float* bq = (const float*)d_in[5];
    const float* Wk = (const float*)d_in[6];  const float* bk = (const float*)d_in[7];
    const float* Wv = (const float*)d_in[8];  const float* bv = (const float*)d_in[9];
    const float* Wo = (const float*)d_in[10]; const float* bo = (const float*)d_in[11];

    float *Qb, *Kb, *Vb;
    __half *Whb, *Chb, *Clb;
    cudaGetSymbolAddress((void**)&Qb, g_Q);
    cudaGetSymbolAddress((void**)&Kb, g_K);
    cudaGetSymbolAddress((void**)&Vb, g_V);
    cudaGetSymbolAddress((void**)&Whb, g_Wh);
    cudaGetSymbolAddress((void**)&Chb, g_Ch);
    cudaGetSymbolAddress((void**)&Clb, g_Cl);

    detect_mask_kernel<<<1, 256>>>((const unsigned int*)mask);
    build_bias_kernel<<<(M_ + 255) / 256, 256>>>(mask);

    RoundBatch rbw;
    rbw.in[0] = Wq; rbw.in[1] = Wk; rbw.in[2] = Wv; rbw.in[3] = Wo;
    round_weights_kernel<<<dim3(DD_/1024, 1, 4), 256>>>(rbw, Whb);

    // QKV projections (A = fp32, split in-kernel)
    GemmBatch gqkv;
    gqkv.A[0] = query; gqkv.A[1] = key; gqkv.A[2] = value;
    gqkv.Al[0] = gqkv.Al[1] = gqkv.Al[2] = nullptr;
    gqkv.Wh[0] = Whb; gqkv.Wh[1] = Whb + DD_; gqkv.Wh[2] = Whb + 2*DD_;
    gqkv.bias[0] = bq; gqkv.bias[1] = bk; gqkv.bias[2] = bv;
    gqkv.C[0] = Qb; gqkv.C[1] = Kb; gqkv.C[2] = Vb;
    gemm_f16x2_kernel<0><<<dim3(D_/128, M_/128, 3), 256>>>(gqkv);

    attn_mma_kernel<<<dim3(T_/128, H_, B_), 256>>>(Qb, Kb, Vb, Chb, Clb);

    // O projection (A = pre-split hi/lo planes from attention)
    GemmBatch go;
    go.A[0] = Chb; go.Al[0] = Clb; go.Wh[0] = Whb + 3*DD_;
    go.bias[0] = bo; go.C[0] = (float*)d_out;
    go.A[1] = Chb; go.Al[1] = Clb; go.Wh[1] = Whb + 3*DD_;
    go.bias[1] = bo; go.C[1] = (float*)d_out;
    go.A[2] = Chb; go.Al[2] = Clb; go.Wh[2] = Whb + 3*DD_;
    go.bias[2] = bo; go.C[2] = (float*)d_out;
    gemm_f16x2_kernel<1><<<dim3(D_/128, M_/128, 1), 256>>>(go);
}